// round 15
// baseline (speedup 1.0000x reference)
#include <cuda_runtime.h>

#define T_STEPS 750
#define B_TOT   1024
#define HID     100
#define KDIM    104      // 100 recurrent + 4 input-drive rows
#define BTILE   2
#define NTHREADS 128
#define NBLOCKS (B_TOT / BTILE)   // 512 CTAs -> 4 CTAs/SM, 4 barrier domains
#define ALPHA   0.01f
#define NSTD    0.1f

__device__ __forceinline__ float tanh_fast(float x) {
    float y;
    asm("tanh.approx.f32 %0, %1;" : "=f"(y) : "f"(x));
    return y;
}
__device__ __forceinline__ unsigned long long pack2(float x) {
    unsigned long long r;
    asm("mov.b64 %0, {%1, %1};" : "=l"(r) : "f"(x));
    return r;
}
__device__ __forceinline__ void ffma2(unsigned long long& d,
                                      unsigned long long a,
                                      unsigned long long b) {
    asm("fma.rn.f32x2 %0, %1, %2, %0;" : "+l"(d) : "l"(a), "l"(b));
}
__device__ __forceinline__ unsigned long long fadd2(unsigned long long a,
                                                    unsigned long long b) {
    unsigned long long r;
    asm("add.rn.f32x2 %0, %1, %2;" : "=l"(r) : "l"(a), "l"(b));
    return r;
}
__device__ __forceinline__ float2 unpack2(unsigned long long v) {
    float2 f;
    asm("mov.b64 {%0, %1}, %2;" : "=f"(f.x), "=f"(f.y) : "l"(v));
    return f;
}

// One RNN step (R5 structure, BTILE=2).  R rows are 8 bytes; one uniform
// LDS.128 per even j yields (R[j][0], R[j][1], R[j+1][0], R[j+1][1]).
__device__ __forceinline__ void rnn_step(
    int tcur, int i, int b0,
    float (&x)[BTILE], const float (&Jreg)[KDIM], float ci,
    const float (&ncur)[BTILE], float ucur,
    float (&nnext)[BTILE], float& unext,
    float (&R)[KDIM][BTILE],
    const float* __restrict__ noise,
    const float* __restrict__ input_seq)
{
    // Phase 1: publish r rows (i < 100) and u rows (100..103, lanes 0..7)
    if (i < HID) {
        float2 r0;
        r0.x = tanh_fast(x[0]);
        r0.y = tanh_fast(x[1]);
        *(float2*)&R[i][0] = r0;
    }
    if (i < 8) R[HID + (i & 3)][i >> 2] = ucur;   // b = i>>2, c = i&3
    __syncthreads();

    // Prefetch next step's noise + input (one full step ahead of use)
    const int tn = (tcur + 1 < T_STEPS) ? (tcur + 1) : tcur;
    {
        const float* np = noise + ((size_t)tn * B_TOT + b0) * HID + i;
#pragma unroll
        for (int b = 0; b < BTILE; b++)
            nnext[b] = (i < HID) ? np[b * HID] : 0.0f;
        if (i < 8)
            unext = input_seq[((size_t)tn * B_TOT + b0 + (i >> 2)) * 4 + (i & 3)];
    }

    // Phase 2: y[b] = sum_j Jreg[j] * R[j][b]  (2 packed accs, even/odd j)
    unsigned long long ya = 0ull, yb = 0ull;
#pragma unroll
    for (int j = 0; j < KDIM; j += 2) {
        ulonglong2 rr = *(const ulonglong2*)&R[j][0];
        ffma2(ya, rr.x, pack2(Jreg[j]));
        ffma2(yb, rr.y, pack2(Jreg[j + 1]));
    }
    __syncthreads();   // all reads of R done before next step overwrites it

    unsigned long long y01 = fadd2(ya, yb);

    // Phase 3: x <- (1-a)x + a*y + a*c + (a*noise_std)*n   (registers only)
    float2 f01 = unpack2(y01);
    float y[BTILE] = { f01.x, f01.y };
#pragma unroll
    for (int b = 0; b < BTILE; b++) {
        x[b] = fmaf(1.0f - ALPHA, x[b],
               fmaf(ALPHA, y[b],
               fmaf(ALPHA * NSTD, ncur[b], ci)));
    }
}

__global__ void __launch_bounds__(NTHREADS, 4)
rnn_kernel(const float* __restrict__ input_seq,
           const float* __restrict__ noise,
           const float* __restrict__ J_w,
           const float* __restrict__ Bmat,
           const float* __restrict__ c_x,
           const float* __restrict__ Wout_w,
           const float* __restrict__ Wout_b,
           float* __restrict__ out)
{
    __shared__ __align__(16) float R[KDIM][BTILE];
    __shared__ float warp_part[4][BTILE];   // epilogue partials

    const int i  = threadIdx.x;            // state row owned by this thread
    const int b0 = blockIdx.x * BTILE;     // batch slice base

    // Row i of [J ; Bmat^T] held permanently in registers (static indexing).
    float Jreg[KDIM];
#pragma unroll
    for (int j = 0; j < KDIM; j++) {
        float v = 0.0f;
        if (i < HID)
            v = (j < HID) ? J_w[i * HID + j] : Bmat[(j - HID) * HID + i];
        Jreg[j] = v;
    }
    const float ci = (i < HID) ? (ALPHA * c_x[i]) : 0.0f;

    float x[BTILE];
#pragma unroll
    for (int b = 0; b < BTILE; b++) x[b] = 0.0f;

    // Preload t=0 noise + input into buffer A
    float nA[BTILE], nB[BTILE];
    float uA = 0.0f, uB = 0.0f;
    {
        const float* np = noise + (size_t)b0 * HID + i;
#pragma unroll
        for (int b = 0; b < BTILE; b++)
            nA[b] = (i < HID) ? np[b * HID] : 0.0f;
        if (i < 8)
            uA = input_seq[((size_t)b0 + (i >> 2)) * 4 + (i & 3)];
    }

    // Main scan, unrolled by 2 for register double-buffering of noise/input
    for (int t = 0; t < T_STEPS; t += 2) {
        rnn_step(t,     i, b0, x, Jreg, ci, nA, uA, nB, uB, R, noise, input_seq);
        rnn_step(t + 1, i, b0, x, Jreg, ci, nB, uB, nA, uA, R, noise, input_seq);
    }

    // Epilogue: out[b] = tanh(x_final[b]) . Wout + bias.
    // Deterministic: butterfly shuffle within warp, fixed-order cross-warp sum.
    {
        const float w = (i < HID) ? Wout_w[i] : 0.0f;
        float part[BTILE];
#pragma unroll
        for (int b = 0; b < BTILE; b++)
            part[b] = (i < HID) ? w * tanhf(x[b]) : 0.0f;
#pragma unroll
        for (int off = 16; off > 0; off >>= 1) {
#pragma unroll
            for (int b = 0; b < BTILE; b++)
                part[b] += __shfl_xor_sync(0xFFFFFFFFu, part[b], off);
        }
        const int warp = i >> 5;
        if ((i & 31) == 0) {
#pragma unroll
            for (int b = 0; b < BTILE; b++)
                warp_part[warp][b] = part[b];
        }
        __syncthreads();
        if (i < BTILE) {
            float s = warp_part[0][i] + warp_part[1][i]
                    + warp_part[2][i] + warp_part[3][i];
            out[b0 + i] = s + Wout_b[0];
        }
    }
}

extern "C" void kernel_launch(void* const* d_in, const int* in_sizes, int n_in,
                              void* d_out, int out_size)
{
    const float* input_seq = (const float*)d_in[0];  // [750,1024,4]
    const float* noise     = (const float*)d_in[1];  // [750,1024,100]
    const float* J_w       = (const float*)d_in[2];  // [100,100]
    const float* Bmat      = (const float*)d_in[3];  // [4,100]
    const float* c_x       = (const float*)d_in[4];  // [100]
    const float* Wout_w    = (const float*)d_in[5];  // [1,100]
    const float* Wout_b    = (const float*)d_in[6];  // [1]
    float* out = (float*)d_out;                      // [1024]

    rnn_kernel<<<NBLOCKS, NTHREADS>>>(
        input_seq, noise, J_w, Bmat, c_x, Wout_w, Wout_b, out);
}

// round 17
// speedup vs baseline: 1.7723x; 1.7723x over previous
#include <cuda_runtime.h>
#include <cuda_bf16.h>
#include <cstdint>

#define T_STEPS 750
#define B_TOT   1024
#define HID     100
#define NB      8            // batch per CTA (= MMA N)
#define NTHREADS 128
#define NBLOCKS (B_TOT / NB) // 128
#define KT      7            // k-tiles of 16 -> K = 112 (104 used)
#define BSTRIDE 136          // bf16 elems per Bsm row (bank-conflict-free)
#define ALPHA   0.01f
#define NSTD    0.1f

__device__ __forceinline__ float tanh_fast(float x) {
    float y;
    asm("tanh.approx.f32 %0, %1;" : "=f"(y) : "f"(x));
    return y;
}
// pack two floats as bf16x2 (element0 in low 16 bits = lower k index)
__device__ __forceinline__ uint32_t pk2(float e0, float e1) {
    __nv_bfloat162 h = __floats2bfloat162_rn(e0, e1);
    return *reinterpret_cast<uint32_t*>(&h);
}
__device__ __forceinline__ float lo_of(float v) {
    return v - __bfloat162float(__float2bfloat16(v));
}
// D = A(16x16) * B(16x8) + D, bf16 in / f32 accumulate
__device__ __forceinline__ void mma16816(float (&d)[4], const uint32_t (&a)[4],
                                         uint32_t b0, uint32_t b1) {
    asm volatile(
        "mma.sync.aligned.m16n8k16.row.col.f32.bf16.bf16.f32 "
        "{%0,%1,%2,%3}, {%4,%5,%6,%7}, {%8,%9}, {%0,%1,%2,%3};"
        : "+f"(d[0]), "+f"(d[1]), "+f"(d[2]), "+f"(d[3])
        : "r"(a[0]), "r"(a[1]), "r"(a[2]), "r"(a[3]), "r"(b0), "r"(b1));
}
__device__ __forceinline__ float getA(const float* J_w, const float* Bmat,
                                      int row, int col) {
    if (row >= HID) return 0.0f;
    if (col < HID)  return J_w[row * HID + col];
    if (col < HID + 4) return Bmat[(col - HID) * HID + row];
    return 0.0f;
}

// One step. x/d layout: thread (w, g=lane>>2, c=lane&3) owns
// rows {32w+16mt+8dd+g}, batches {2c, 2c+1}; x[4mt+2dd+e].
__device__ __forceinline__ void rnn_step(
    int t, int w, int g, int c, int b0,
    float (&x)[8],
    const uint32_t (&Ah)[2][KT][4], const uint32_t (&Al)[2][KT][4],
    const float (&ci)[4],
    const float (&nc)[8], float (&nn)[8], float uc, float& un,
    __nv_bfloat16 (&Bh)[NB][BSTRIDE], __nv_bfloat16 (&Bl)[NB][BSTRIDE],
    const float* __restrict__ noise, const float* __restrict__ input_seq)
{
    __syncthreads();   // B(t) visible to all warps

    // B fragment loads (conflict-free) + 3-pass MMA, 6 independent chains
    float dh[2][4] = {}, dm[2][4] = {}, dl[2][4] = {};
#pragma unroll
    for (int kt = 0; kt < KT; kt++) {
        const int k0 = 16 * kt + 2 * c;
        const uint32_t bh0 = *(const uint32_t*)&Bh[g][k0];
        const uint32_t bh1 = *(const uint32_t*)&Bh[g][k0 + 8];
        const uint32_t bl0 = *(const uint32_t*)&Bl[g][k0];
        const uint32_t bl1 = *(const uint32_t*)&Bl[g][k0 + 8];
#pragma unroll
        for (int mt = 0; mt < 2; mt++) {
            mma16816(dh[mt], Ah[mt][kt], bh0, bh1);
            mma16816(dm[mt], Ah[mt][kt], bl0, bl1);
            mma16816(dl[mt], Al[mt][kt], bh0, bh1);
        }
    }

    // prefetch noise(t+1) and u(t+2) (independent of MMA results)
    const int tn = (t + 1 < T_STEPS) ? t + 1 : t;
#pragma unroll
    for (int mt = 0; mt < 2; mt++)
#pragma unroll
        for (int dd = 0; dd < 2; dd++)
#pragma unroll
            for (int e = 0; e < 2; e++) {
                const int row = 32 * w + 16 * mt + 8 * dd + g;
                const int idx = 4 * mt + 2 * dd + e;
                nn[idx] = (row < HID)
                    ? noise[((size_t)tn * B_TOT + b0 + 2 * c + e) * HID + row]
                    : 0.0f;
            }
    if (w == 0) {
        const int tu = (t + 2 < T_STEPS) ? t + 2 : T_STEPS - 1;
        un = input_seq[((size_t)tu * B_TOT + b0 + g) * 4 + c];
    }

    __syncthreads();   // all B(t) reads done; B(t+1) writes may begin

    // x update + publish B(t+1) = [split(tanh(x_new)) ; split(u(t+1))]
#pragma unroll
    for (int mt = 0; mt < 2; mt++)
#pragma unroll
        for (int dd = 0; dd < 2; dd++)
#pragma unroll
            for (int e = 0; e < 2; e++) {
                const int row = 32 * w + 16 * mt + 8 * dd + g;
                const int idx = 4 * mt + 2 * dd + e;
                const int dj  = 2 * dd + e;
                const float y = dh[mt][dj] + dm[mt][dj] + dl[mt][dj];
                x[idx] = fmaf(1.0f - ALPHA, x[idx],
                         fmaf(ALPHA, y,
                         fmaf(ALPHA * NSTD, nc[idx], ci[2 * mt + dd])));
                if (row < HID) {
                    const float r = tanh_fast(x[idx]);
                    const __nv_bfloat16 hi = __float2bfloat16(r);
                    Bh[2 * c + e][row] = hi;
                    Bl[2 * c + e][row] =
                        __float2bfloat16(r - __bfloat162float(hi));
                }
            }
    if (w == 0) {   // u(t+1) into k-rows 100..103, batch g
        const __nv_bfloat16 hi = __float2bfloat16(uc);
        Bh[g][HID + c] = hi;
        Bl[g][HID + c] = __float2bfloat16(uc - __bfloat162float(hi));
    }
}

__global__ void __launch_bounds__(NTHREADS, 1)
rnn_kernel(const float* __restrict__ input_seq,
           const float* __restrict__ noise,
           const float* __restrict__ J_w,
           const float* __restrict__ Bmat,
           const float* __restrict__ c_x,
           const float* __restrict__ Wout_w,
           const float* __restrict__ Wout_b,
           float* __restrict__ out)
{
    __shared__ __align__(16) __nv_bfloat16 Bh[NB][BSTRIDE];
    __shared__ __align__(16) __nv_bfloat16 Bl[NB][BSTRIDE];
    __shared__ float warp_part[4][NB];

    const int tid  = threadIdx.x;
    const int w    = tid >> 5;
    const int lane = tid & 31;
    const int g    = lane >> 2;    // 0..7
    const int c    = lane & 3;     // 0..3
    const int b0   = blockIdx.x * NB;

    // zero B staging (k-pad rows 104..111 must stay 0 forever)
    for (int i = tid; i < NB * BSTRIDE; i += NTHREADS) {
        ((__nv_bfloat16*)Bh)[i] = __float2bfloat16(0.0f);
        ((__nv_bfloat16*)Bl)[i] = __float2bfloat16(0.0f);
    }

    // A = [J ; Bmat^T] in mma fragment layout, hi/lo split, registers forever
    uint32_t Ah[2][KT][4], Al[2][KT][4];
#pragma unroll
    for (int mt = 0; mt < 2; mt++)
#pragma unroll
        for (int kt = 0; kt < KT; kt++) {
            const int r0 = 32 * w + 16 * mt + g, r1 = r0 + 8;
            const int kc = 16 * kt + 2 * c;
            const float v00 = getA(J_w, Bmat, r0, kc);
            const float v01 = getA(J_w, Bmat, r0, kc + 1);
            const float v10 = getA(J_w, Bmat, r1, kc);
            const float v11 = getA(J_w, Bmat, r1, kc + 1);
            const float v02 = getA(J_w, Bmat, r0, kc + 8);
            const float v03 = getA(J_w, Bmat, r0, kc + 9);
            const float v12 = getA(J_w, Bmat, r1, kc + 8);
            const float v13 = getA(J_w, Bmat, r1, kc + 9);
            Ah[mt][kt][0] = pk2(v00, v01);
            Ah[mt][kt][1] = pk2(v10, v11);
            Ah[mt][kt][2] = pk2(v02, v03);
            Ah[mt][kt][3] = pk2(v12, v13);
            Al[mt][kt][0] = pk2(lo_of(v00), lo_of(v01));
            Al[mt][kt][1] = pk2(lo_of(v10), lo_of(v11));
            Al[mt][kt][2] = pk2(lo_of(v02), lo_of(v03));
            Al[mt][kt][3] = pk2(lo_of(v12), lo_of(v13));
        }

    // alpha-scaled bias per owned row group
    float ci[4];
#pragma unroll
    for (int mt = 0; mt < 2; mt++)
#pragma unroll
        for (int dd = 0; dd < 2; dd++) {
            const int row = 32 * w + 16 * mt + 8 * dd + g;
            ci[2 * mt + dd] = (row < HID) ? ALPHA * c_x[row] : 0.0f;
        }

    float x[8];
#pragma unroll
    for (int i = 0; i < 8; i++) x[i] = 0.0f;

    // noise(0) into nc
    float nc[8], nn[8];
#pragma unroll
    for (int mt = 0; mt < 2; mt++)
#pragma unroll
        for (int dd = 0; dd < 2; dd++)
#pragma unroll
            for (int e = 0; e < 2; e++) {
                const int row = 32 * w + 16 * mt + 8 * dd + g;
                const int idx = 4 * mt + 2 * dd + e;
                nc[idx] = (row < HID)
                    ? noise[((size_t)b0 + 2 * c + e) * HID + row] : 0.0f;
            }

    // publish B(0): r rows are zero (already), u(0) rows; preload u(1)
    float uc = 0.0f, un = 0.0f;
    if (w == 0) {
        const float u0 = input_seq[(size_t)(b0 + g) * 4 + c];
        const __nv_bfloat16 hi = __float2bfloat16(u0);
        Bh[g][HID + c] = hi;
        Bl[g][HID + c] = __float2bfloat16(u0 - __bfloat162float(hi));
        uc = input_seq[((size_t)1 * B_TOT + b0 + g) * 4 + c];   // u(1)
    }

    // main scan (unroll-2: noise/u register ping-pong)
    for (int t = 0; t < T_STEPS; t += 2) {
        rnn_step(t,     w, g, c, b0, x, Ah, Al, ci, nc, nn, uc, un,
                 Bh, Bl, noise, input_seq);
        rnn_step(t + 1, w, g, c, b0, x, Ah, Al, ci, nn, nc, un, uc,
                 Bh, Bl, noise, input_seq);
    }

    // epilogue: out[b] = sum_row Wout[row]*tanh(x) + bias (deterministic)
    {
        float p[2] = { 0.0f, 0.0f };
#pragma unroll
        for (int mt = 0; mt < 2; mt++)
#pragma unroll
            for (int dd = 0; dd < 2; dd++)
#pragma unroll
                for (int e = 0; e < 2; e++) {
                    const int row = 32 * w + 16 * mt + 8 * dd + g;
                    if (row < HID)
                        p[e] += Wout_w[row] * tanhf(x[4 * mt + 2 * dd + e]);
                }
        // reduce over g (lane bits 2..4); all lanes keep same-c sums
#pragma unroll
        for (int off = 4; off <= 16; off <<= 1) {
            p[0] += __shfl_xor_sync(0xFFFFFFFFu, p[0], off);
            p[1] += __shfl_xor_sync(0xFFFFFFFFu, p[1], off);
        }
        if (g == 0) {
            warp_part[w][2 * c]     = p[0];
            warp_part[w][2 * c + 1] = p[1];
        }
        __syncthreads();
        if (tid < NB) {
            out[b0 + tid] = warp_part[0][tid] + warp_part[1][tid]
                          + warp_part[2][tid] + warp_part[3][tid] + Wout_b[0];
        }
    }
}

extern "C" void kernel_launch(void* const* d_in, const int* in_sizes, int n_in,
                              void* d_out, int out_size)
{
    const float* input_seq = (const float*)d_in[0];  // [750,1024,4]
    const float* noise     = (const float*)d_in[1];  // [750,1024,100]
    const float* J_w       = (const float*)d_in[2];  // [100,100]
    const float* Bmat      = (const float*)d_in[3];  // [4,100]
    const float* c_x       = (const float*)d_in[4];  // [100]
    const float* Wout_w    = (const float*)d_in[5];  // [1,100]
    const float* Wout_b    = (const float*)d_in[6];  // [1]
    float* out = (float*)d_out;                      // [1024]

    rnn_kernel<<<NBLOCKS, NTHREADS>>>(
        input_seq, noise, J_w, Bmat, c_x, Wout_w, Wout_b, out);
}